// round 8
// baseline (speedup 1.0000x reference)
#include <cuda_runtime.h>
#include <cuda_bf16.h>
#include <math.h>

// Problem dims (fixed)
#define HH 768
#define G3 2304          // 3*H
#define BB 64            // batch
#define LL 512           // seq len
#define NSTEP 513        // 512 steps + final end-token step
#define NROWS (NSTEP*BB)

// fused persistent kernel: 148 co-resident blocks (GB300 has 152 SMs, B300 148)
#define NTOT 148
#define NREC 96          // recurrence blocks (768/96 = 8 units each)
#define RTPB 256
#define UPB  8           // hidden units per rec block
#define RC   24          // gh cols per rec block = 3*UPB
#define CHK  256         // staged k rows per buffer (768 = 3*256)
#define GTILES 18        // gi col tiles per step (2304/128)
#define NJOB (NSTEP*GTILES)

// Scratch (device globals — allocation-free rule)
static __device__ __align__(256) float g_giT[(size_t)NROWS * G3];  // gi transposed: [l][G3 unit][64 b]
static __device__ __align__(256) float g_hT[HH * BB];              // h transposed [k][b]
static __device__ __align__(256) float g_hbm[BB * HH];             // final h [b][k] for scorer
static __device__ __align__(256) float g_s1[BB * HH];
static __device__ __align__(256) float g_s2[BB * HH];
static __device__ unsigned g_leaf[12];                             // monotonic leaf counters (12 x 8)
static __device__ unsigned g_master = 0;                           // monotonic master counter
static __device__ unsigned g_gen    = 0;                           // monotonic generation
static __device__ unsigned g_job    = 0;                           // gi job queue (reset each replay)
static __device__ unsigned g_done[NSTEP];                          // gi tiles done per step (reset)

// ---------------------------------------------------------------------------
// packed fp32 helpers (sm_103a f32x2)
__device__ __forceinline__ void ffma2(unsigned long long& d,
                                      unsigned long long a, unsigned long long b)
{
    asm("fma.rn.f32x2 %0, %1, %2, %0;" : "+l"(d) : "l"(a), "l"(b));
}
__device__ __forceinline__ unsigned long long pack2(float x)
{
    unsigned long long r;
    asm("mov.b64 %0, {%1, %1};" : "=l"(r) : "f"(x));
    return r;
}
__device__ __forceinline__ float2 unpk2(unsigned long long v)
{
    float2 f;
    asm("mov.b64 {%0, %1}, %2;" : "=f"(f.x), "=f"(f.y) : "l"(v));
    return f;
}
__device__ __forceinline__ void cpa16(unsigned dst, const void* src)
{
    asm volatile("cp.async.cg.shared.global [%0], [%1], 16;" :: "r"(dst), "l"(src));
}
__device__ __forceinline__ void cpa_commit() { asm volatile("cp.async.commit_group;" ::: "memory"); }
__device__ __forceinline__ void cpa_wait0()  { asm volatile("cp.async.wait_group 0;" ::: "memory"); }
__device__ __forceinline__ void cpa_wait1()  { asm volatile("cp.async.wait_group 1;" ::: "memory"); }

__device__ __forceinline__ float sigmoidf_(float x)
{
    return 1.f / (1.f + __expf(-x));
}

// ---------------------------------------------------------------------------
__global__ void k_init()
{
    int t = blockIdx.x * blockDim.x + threadIdx.x;
    if (t < BB * HH) g_hT[t] = 0.f;
    if (t < NSTEP) g_done[t] = 0u;
    if (t == 0) g_job = 0u;
}

// ---------------------------------------------------------------------------
// Two-level grid barrier among NREC blocks: 12 leaves x 8 -> master -> gen.
__device__ __forceinline__ void gsync(unsigned target, int bid)
{
    __syncthreads();
    if (threadIdx.x == 0) {
        unsigned old;
        asm volatile("atom.acq_rel.gpu.global.add.u32 %0, [%1], %2;"
                     : "=r"(old) : "l"(g_leaf + (bid >> 3)), "r"(1u) : "memory");
        if ((old & 7u) == 7u) {
            unsigned o2;
            asm volatile("atom.acq_rel.gpu.global.add.u32 %0, [%1], %2;"
                         : "=r"(o2) : "l"(&g_master), "r"(1u) : "memory");
            if (o2 % 12u == 11u)
                asm volatile("st.release.gpu.global.u32 [%0], %1;"
                             :: "l"(&g_gen), "r"(target) : "memory");
        }
        unsigned g;
        do {
            asm volatile("ld.acquire.gpu.global.u32 %0, [%1];"
                         : "=r"(g) : "l"(&g_gen) : "memory");
        } while ((int)(g - target) < 0);
    }
    __syncthreads();
}

// ---------------------------------------------------------------------------
// gi producer (blocks NREC..NTOT-1): job queue over (step, 128-unit tile).
// Tile 128 units x 64 batch, K=768. 256 threads, thread tile 8u x 4b.
__device__ void gi_producer(float* sm,
                            const int* __restrict__ goal,
                            const float* __restrict__ emb,
                            const float* __restrict__ w_ih,
                            const float* __restrict__ b_ih)
{
    float* As = sm;              // [16][128] units x k
    float* Bs = sm + 16 * 128;   // [16][64]  batch x k
    __shared__ int tok[BB];
    __shared__ unsigned sjob;

    const int tid = threadIdx.x;
    const int ug = tid & 15;     // units ug*8..+7
    const int bg = tid >> 4;     // batch bg*4..+3

    for (;;) {
        if (tid == 0) sjob = atomicAdd(&g_job, 1u);
        __syncthreads();
        const unsigned j = sjob;
        if (j >= NJOB) break;
        const int by = (int)(j / GTILES);
        const int n0 = (int)(j % GTILES) * 128;
        const bool seq = (by < LL);

        if (tid < BB) tok[tid] = seq ? goal[tid * LL + by] : 1;
        __syncthreads();

        unsigned long long acc[4][4];
#pragma unroll
        for (int p = 0; p < 4; p++)
#pragma unroll
            for (int c = 0; c < 4; c++) acc[p][c] = 0ull;

        float4 vw[2], ve;
        auto loadW = [&](float4 v[2], int k0) {
#pragma unroll
            for (int q = 0; q < 2; q++) {
                int f = tid + 256 * q;
                int r = f >> 2, kk = (f & 3) * 4;
                v[q] = *(const float4*)(w_ih + (size_t)(n0 + r) * HH + k0 + kk);
            }
        };
        auto loadE = [&](float4& v, int k0) {
            int r = tid >> 2, kk = (tid & 3) * 4;
            v = *(const float4*)(emb + (size_t)tok[r] * HH + k0 + kk);
            if (seq) {
                v.x = fmaxf(v.x, 0.f); v.y = fmaxf(v.y, 0.f);
                v.z = fmaxf(v.z, 0.f); v.w = fmaxf(v.w, 0.f);
            }
        };
        auto storeW = [&](const float4 v[2]) {
#pragma unroll
            for (int q = 0; q < 2; q++) {
                int f = tid + 256 * q;
                int r = f >> 2, kk = (f & 3) * 4;
                As[kk * 128 + r]       = v[q].x;
                As[(kk + 1) * 128 + r] = v[q].y;
                As[(kk + 2) * 128 + r] = v[q].z;
                As[(kk + 3) * 128 + r] = v[q].w;
            }
        };
        auto storeE = [&](const float4& v) {
            int r = tid >> 2, kk = (tid & 3) * 4;
            Bs[kk * 64 + r]       = v.x;
            Bs[(kk + 1) * 64 + r] = v.y;
            Bs[(kk + 2) * 64 + r] = v.z;
            Bs[(kk + 3) * 64 + r] = v.w;
        };

        loadW(vw, 0); loadE(ve, 0);
        storeW(vw);   storeE(ve);
        __syncthreads();

        for (int t = 0; t < HH / 16; t++) {
            float4 nw[2], ne;
            if (t < HH / 16 - 1) { loadW(nw, (t + 1) * 16); loadE(ne, (t + 1) * 16); }
#pragma unroll 4
            for (int k = 0; k < 16; k++) {
                ulonglong2 a0 = *(const ulonglong2*)&As[k * 128 + ug * 8];
                ulonglong2 a1 = *(const ulonglong2*)&As[k * 128 + ug * 8 + 4];
                float4 e = *(const float4*)&Bs[k * 64 + bg * 4];
                unsigned long long ap[4] = {a0.x, a0.y, a1.x, a1.y};
                unsigned long long bp[4] = {pack2(e.x), pack2(e.y), pack2(e.z), pack2(e.w)};
#pragma unroll
                for (int p = 0; p < 4; p++)
#pragma unroll
                    for (int c = 0; c < 4; c++) ffma2(acc[p][c], ap[p], bp[c]);
            }
            __syncthreads();
            if (t < HH / 16 - 1) { storeW(nw); storeE(ne); }
            __syncthreads();
        }

        // epilogue: giT[(by*G3 + u)*64 + b], + per-unit bias
#pragma unroll
        for (int p = 0; p < 4; p++) {
            const int u = n0 + ug * 8 + 2 * p;
            const float bia0 = b_ih[u], bia1 = b_ih[u + 1];
            float2 v[4];
#pragma unroll
            for (int c = 0; c < 4; c++) v[c] = unpk2(acc[p][c]);
            float* d0 = g_giT + ((size_t)by * G3 + u) * BB + bg * 4;
            float* d1 = d0 + BB;
            *(float4*)d0 = make_float4(v[0].x + bia0, v[1].x + bia0, v[2].x + bia0, v[3].x + bia0);
            *(float4*)d1 = make_float4(v[0].y + bia1, v[1].y + bia1, v[2].y + bia1, v[3].y + bia1);
        }

        // publish: stores -> fence -> count
        __syncthreads();
        if (tid == 0) {
            __threadfence();
            atomicAdd(&g_done[by], 1u);
        }
    }
}

// ---------------------------------------------------------------------------
// Recurrence consumer (blocks 0..NREC-1). UPB=8 units, RC=24 gh cols, 8-warp
// k-split, single grid barrier per step, waits on gi producer flags.
__device__ void rec_consumer(float* sm, int bid,
                             const float* __restrict__ w_hh,
                             const float* __restrict__ b_hh)
{
    float* ws  = sm;                       // [768][24]
    float* hs  = sm + HH * RC;             // 2 x [256][64]
    float* red = hs + CHK * BB;            // alias buf1 (free at reduction time)
    float* ghs = hs + 2 * CHK * BB;        // [64][24]

    const int tid  = threadIdx.x;
    const int u0   = bid * UPB;
    const int w    = tid >> 5;             // warp = k-slice 0..7
    const int lane = tid & 31;
    const int rg   = lane & 7;             // rows rg*8..+7 (4 pairs)
    const int cg   = lane >> 3;            // cols cg*6..+5

    // preload w slice: ws[k*24 + c], c = gate*8+unit
    for (int idx = tid; idx < HH * RC; idx += RTPB) {
        int k = idx / RC, c = idx - k * RC;
        int g = c >> 3, i = c & 7;
        ws[idx] = w_hh[(size_t)(g * HH + u0 + i) * HH + k];
    }
    // gate biases: t = tid + q*256 -> b = t&63, iu = t>>6
    float bh_r[2], bh_z[2], bh_n[2];
#pragma unroll
    for (int q = 0; q < 2; q++) {
        int iu = (tid + q * RTPB) >> 6;
        bh_r[q] = b_hh[u0 + iu];
        bh_z[q] = b_hh[HH + u0 + iu];
        bh_n[q] = b_hh[2 * HH + u0 + iu];
    }
    __syncthreads();

    const unsigned hsb = (unsigned)__cvta_generic_to_shared(hs);
    auto stage = [&](int ch) {
        const float4* src = (const float4*)(g_hT + (size_t)ch * CHK * BB) + tid;
        unsigned dst = hsb + (unsigned)((ch & 1) * (CHK * BB * 4)) + tid * 16;
#pragma unroll
        for (int j = 0; j < (CHK * BB / 4) / RTPB; j++)   // 16
            cpa16(dst + j * RTPB * 16, src + j * RTPB);
        cpa_commit();
    };

    const unsigned base = *(volatile unsigned*)&g_gen;    // replay-safe offset
    unsigned ngen = 0;

    for (int l = 0; l < NSTEP; l++) {
        stage(0);
        stage(1);

        // wait for gi of this step (producers publish with release)
        if (tid == 0) {
            unsigned d;
            do {
                asm volatile("ld.acquire.gpu.global.u32 %0, [%1];"
                             : "=r"(d) : "l"(&g_done[l]) : "memory");
                if (d < GTILES) __nanosleep(64);
            } while (d < GTILES);
        }
        __syncthreads();

        // prefetch gate operands (batch-contiguous)
        float pre_r[2], pre_z[2], pre_n[2], pre_h[2];
#pragma unroll
        for (int q = 0; q < 2; q++) {
            int t = tid + q * RTPB;
            int b = t & 63, iu = t >> 6;
            const float* gp = g_giT + ((size_t)l * G3 + u0 + iu) * BB + b;
            pre_r[q] = __ldcg(gp);
            pre_z[q] = __ldcg(gp + (size_t)HH * BB);
            pre_n[q] = __ldcg(gp + (size_t)2 * HH * BB);
            pre_h[q] = __ldcg(&g_hT[(u0 + iu) * BB + b]);
        }

        unsigned long long acc[4][6];
#pragma unroll
        for (int p = 0; p < 4; p++)
#pragma unroll
            for (int c = 0; c < 6; c++) acc[p][c] = 0ull;

        for (int ch = 0; ch < HH / CHK; ch++) {
            if (ch < HH / CHK - 1) cpa_wait1(); else cpa_wait0();
            __syncthreads();
            const float* hb = hs + (ch & 1) * (CHK * BB);
            const int kb = w * (CHK / 8);
#pragma unroll 2
            for (int kk = 0; kk < CHK / 8; kk++) {
                const int kl = kb + kk;
                const int kg = ch * CHK + kl;
                ulonglong2 a0 = *(const ulonglong2*)&hb[kl * BB + rg * 8];
                ulonglong2 a1 = *(const ulonglong2*)&hb[kl * BB + rg * 8 + 4];
                const float* wp = &ws[kg * RC + cg * 6];
                float2 w01 = *(const float2*)(wp);
                float2 w23 = *(const float2*)(wp + 2);
                float2 w45 = *(const float2*)(wp + 4);
                unsigned long long ap[4] = {a0.x, a0.y, a1.x, a1.y};
                unsigned long long bp[6] = {pack2(w01.x), pack2(w01.y), pack2(w23.x),
                                            pack2(w23.y), pack2(w45.x), pack2(w45.y)};
#pragma unroll
                for (int p = 0; p < 4; p++)
#pragma unroll
                    for (int c = 0; c < 6; c++) ffma2(acc[p][c], ap[p], bp[c]);
            }
            __syncthreads();                 // buffer (ch&1) free
            if (ch == 0) stage(2);           // chunk2 -> buf0
        }

        // ---- k-split reduction: red[w][64][24] (buf1), then ghs[64][24] ----
#pragma unroll
        for (int p = 0; p < 4; p++) {
            const int m0 = rg * 8 + 2 * p;
#pragma unroll
            for (int c = 0; c < 6; c++) {
                float2 v = unpk2(acc[p][c]);
                red[w * (BB * RC) + m0 * RC + cg * 6 + c]       = v.x;
                red[w * (BB * RC) + (m0 + 1) * RC + cg * 6 + c] = v.y;
            }
        }
        __syncthreads();
#pragma unroll
        for (int j = 0; j < (BB * RC) / RTPB; j++) {      // 6/thread
            const int o = tid + j * RTPB;
            float s = red[o];
#pragma unroll
            for (int ww = 1; ww < 8; ww++) s += red[ww * (BB * RC) + o];
            ghs[o] = s;
        }
        __syncthreads();

        // ---- gates (block-local) ----
#pragma unroll
        for (int q = 0; q < 2; q++) {
            const int t = tid + q * RTPB;
            const int b = t & 63, iu = t >> 6;
            float ghr = ghs[b * RC + iu];
            float ghz = ghs[b * RC + UPB + iu];
            float ghn = ghs[b * RC + 2 * UPB + iu];
            float r = sigmoidf_(pre_r[q] + ghr + bh_r[q]);
            float z = sigmoidf_(pre_z[q] + ghz + bh_z[q]);
            float n = tanhf(pre_n[q] + r * (ghn + bh_n[q]));
            float h = (1.f - z) * n + z * pre_h[q];
            if (l < LL) h = fmaxf(h, 0.f);       // final step NOT relu'd
            __stcg(&g_hT[(u0 + iu) * BB + b], h);
            if (l == LL) g_hbm[(size_t)b * HH + u0 + iu] = h;
        }

        ++ngen;
        gsync(base + ngen, bid);   // ONE barrier per step (rec blocks only)
    }
}

// ---------------------------------------------------------------------------
__global__ void __launch_bounds__(RTPB, 1) k_fused(const int* __restrict__ goal,
                                                   const float* __restrict__ emb,
                                                   const float* __restrict__ w_ih,
                                                   const float* __restrict__ b_ih,
                                                   const float* __restrict__ w_hh,
                                                   const float* __restrict__ b_hh)
{
    extern __shared__ __align__(16) float sm[];
    if (blockIdx.x < NREC) rec_consumer(sm, blockIdx.x, w_hh, b_hh);
    else                   gi_producer(sm, goal, emb, w_ih, b_ih);
}

// ---------------------------------------------------------------------------
// Scorer (device globals referenced directly in device code)
__global__ void __launch_bounds__(256) k_mlp0(const float* __restrict__ w,
                                              const float* __restrict__ bias)
{
    const int warp = threadIdx.x >> 5;
    const int lane = threadIdx.x & 31;
    const int n = blockIdx.x * 8 + warp;

    float4 wr[6];
    const float* wrow = w + (size_t)n * HH + lane * 24;
#pragma unroll
    for (int i = 0; i < 6; i++) wr[i] = *(const float4*)(wrow + i * 4);
    const float bn = bias[n];

    for (int b = 0; b < BB; b++) {
        const float* xr = g_hbm + (size_t)b * HH + lane * 24;
        float s = 0.f;
#pragma unroll
        for (int i = 0; i < 6; i++) {
            float4 xv = *(const float4*)(xr + i * 4);
            s += xv.x * wr[i].x + xv.y * wr[i].y + xv.z * wr[i].z + xv.w * wr[i].w;
        }
#pragma unroll
        for (int off = 16; off; off >>= 1) s += __shfl_xor_sync(0xffffffffu, s, off);
        if (lane == 0) g_s1[(size_t)b * HH + n] = fmaxf(s + bn, 0.f);
    }
}

__global__ void __launch_bounds__(256) k_mlp1(const float* __restrict__ w,
                                              const float* __restrict__ bias)
{
    const int warp = threadIdx.x >> 5;
    const int lane = threadIdx.x & 31;
    const int n = blockIdx.x * 8 + warp;

    float4 wr[6];
    const float* wrow = w + (size_t)n * HH + lane * 24;
#pragma unroll
    for (int i = 0; i < 6; i++) wr[i] = *(const float4*)(wrow + i * 4);
    const float bn = bias[n];

    for (int b = 0; b < BB; b++) {
        const float* xr = g_s1 + (size_t)b * HH + lane * 24;
        float s = 0.f;
#pragma unroll
        for (int i = 0; i < 6; i++) {
            float4 xv = *(const float4*)(xr + i * 4);
            s += xv.x * wr[i].x + xv.y * wr[i].y + xv.z * wr[i].z + xv.w * wr[i].w;
        }
#pragma unroll
        for (int off = 16; off; off >>= 1) s += __shfl_xor_sync(0xffffffffu, s, off);
        if (lane == 0) g_s2[(size_t)b * HH + n] = fmaxf(s + bn, 0.f);
    }
}

__global__ void __launch_bounds__(256) k_final(const float* __restrict__ swo,
                                               const float* __restrict__ sbo,
                                               float* __restrict__ out)
{
    const int warp = threadIdx.x >> 5;
    const int lane = threadIdx.x & 31;
    const int b = blockIdx.x * 8 + warp;
    const float* xr = g_s2 + (size_t)b * HH + lane * 24;
    const float* wr = swo + lane * 24;
    float s = 0.f;
#pragma unroll
    for (int i = 0; i < 6; i++) {
        float4 xv = *(const float4*)(xr + i * 4);
        float4 wv = *(const float4*)(wr + i * 4);
        s += xv.x * wv.x + xv.y * wv.y + xv.z * wv.z + xv.w * wv.w;
    }
#pragma unroll
    for (int off = 16; off; off >>= 1) s += __shfl_xor_sync(0xffffffffu, s, off);
    if (lane == 0) out[b] = s + sbo[0];
}

// ---------------------------------------------------------------------------
extern "C" void kernel_launch(void* const* d_in, const int* in_sizes, int n_in,
                              void* d_out, int out_size)
{
    const int*   goal = (const int*)  d_in[0];
    const float* emb  = (const float*)d_in[1];
    const float* w_ih = (const float*)d_in[2];
    const float* w_hh = (const float*)d_in[3];
    const float* b_ih = (const float*)d_in[4];
    const float* b_hh = (const float*)d_in[5];
    const float* sw0  = (const float*)d_in[6];
    const float* sb0  = (const float*)d_in[7];
    const float* sw1  = (const float*)d_in[8];
    const float* sb1  = (const float*)d_in[9];
    const float* swo  = (const float*)d_in[10];
    const float* sbo  = (const float*)d_in[11];
    float* out = (float*)d_out;

    const int smem_f = (HH * RC + 2 * CHK * BB + BB * RC) * (int)sizeof(float); // 206KB
    cudaFuncSetAttribute(k_fused, cudaFuncAttributeMaxDynamicSharedMemorySize, smem_f);

    k_init<<<(BB * HH + 255) / 256, 256>>>();
    k_fused<<<NTOT, RTPB, smem_f>>>(goal, emb, w_ih, b_ih, w_hh, b_hh);
    k_mlp0<<<HH / 8, 256>>>(sw0, sb0);
    k_mlp1<<<HH / 8, 256>>>(sw1, sb1);
    k_final<<<BB / 8, 256>>>(swo, sbo, out);
}

// round 11
// speedup vs baseline: 1.8108x; 1.8108x over previous
#include <cuda_runtime.h>
#include <cuda_bf16.h>
#include <math.h>

// Problem dims (fixed)
#define HH 768
#define G3 2304          // 3*H
#define BB 64            // batch
#define LL 512           // seq len
#define NSTEP 513        // 512 steps + final end-token step
#define NROWS (NSTEP*BB)

// recurrence kernel config
#define RBLK 128         // persistent blocks (16 leaves x 8)
#define RTPB 256
#define UPB  6           // hidden units per block (128*6=768)
#define RC   18          // gh cols per block = 3*UPB
#define RCP  24          // padded ws row: 2 groups x 12 (9 used)
#define CHK  256         // staged k rows per buffer (768 = 3*256)
#define KSL  16          // k slices (half-warps)

// Scratch (device globals — allocation-free rule)
static __device__ __align__(256) float g_giT[(size_t)NROWS * G3];  // gi transposed: [l][G3 unit][64 b]
static __device__ __align__(256) float g_hT[HH * BB];              // h transposed [k][b]
static __device__ __align__(256) float g_hbm[BB * HH];             // final h [b][k] for scorer
static __device__ __align__(256) float g_s1[BB * HH];
static __device__ __align__(256) float g_s2[BB * HH];
static __device__ unsigned g_leaf[16];                             // monotonic leaf counters
static __device__ unsigned g_master = 0;                           // monotonic master counter
static __device__ unsigned g_gen    = 0;                           // monotonic generation

// ---------------------------------------------------------------------------
// packed fp32 helpers (sm_103a f32x2)
__device__ __forceinline__ void ffma2(unsigned long long& d,
                                      unsigned long long a, unsigned long long b)
{
    asm("fma.rn.f32x2 %0, %1, %2, %0;" : "+l"(d) : "l"(a), "l"(b));
}
__device__ __forceinline__ unsigned long long pack2(float x)
{
    unsigned long long r;
    asm("mov.b64 %0, {%1, %1};" : "=l"(r) : "f"(x));
    return r;
}
__device__ __forceinline__ float2 unpk2(unsigned long long v)
{
    float2 f;
    asm("mov.b64 {%0, %1}, %2;" : "=f"(f.x), "=f"(f.y) : "l"(v));
    return f;
}
__device__ __forceinline__ void cpa16(unsigned dst, const void* src)
{
    asm volatile("cp.async.cg.shared.global [%0], [%1], 16;" :: "r"(dst), "l"(src));
}
__device__ __forceinline__ void cpa_commit() { asm volatile("cp.async.commit_group;" ::: "memory"); }
__device__ __forceinline__ void cpa_wait0()  { asm volatile("cp.async.wait_group 0;" ::: "memory"); }
__device__ __forceinline__ void cpa_wait1()  { asm volatile("cp.async.wait_group 1;" ::: "memory"); }

__device__ __forceinline__ float sigmoidf_(float x)
{
    return 1.f / (1.f + __expf(-x));
}

// ---------------------------------------------------------------------------
__global__ void k_init()
{
    int t = blockIdx.x * blockDim.x + threadIdx.x;
    if (t < BB * HH) g_hT[t] = 0.f;
}

// ---------------------------------------------------------------------------
// giT[l][unit][b] = relu_if_seq(emb[token(b,l)]) . w_ih[unit,:] + b_ih[unit]
// (identical to R7 — proven)
__global__ void __launch_bounds__(128) k_gi(const int* __restrict__ goal,
                                            const float* __restrict__ emb,
                                            const float* __restrict__ w_ih,
                                            const float* __restrict__ b_ih)
{
    __shared__ __align__(16) float As[16][128];   // units x k
    __shared__ __align__(16) float Bs[16][64];    // batch x k
    __shared__ int tok[64];

    const int by  = blockIdx.y;        // step index
    const int n0  = blockIdx.x * 128;  // unit base
    const int tid = threadIdx.x;
    const bool seq = (by < LL);

    if (tid < 64) tok[tid] = seq ? goal[tid * LL + by] : 1;
    __syncthreads();

    const int ug = tid & 15;           // unit group -> units ug*8..+7
    const int bg = tid >> 4;           // batch group -> batch bg*8..+7

    float4 vw[4], ve[2];
    auto loadW = [&](float4 v[4], int k0) {
#pragma unroll
        for (int q = 0; q < 4; q++) {
            int f = tid + 128 * q;
            int r = f >> 2, kk = (f & 3) * 4;
            v[q] = *(const float4*)(w_ih + (size_t)(n0 + r) * HH + k0 + kk);
        }
    };
    auto loadE = [&](float4 v[2], int k0) {
#pragma unroll
        for (int q = 0; q < 2; q++) {
            int f = tid + 128 * q;
            int r = f >> 2, kk = (f & 3) * 4;
            v[q] = *(const float4*)(emb + (size_t)tok[r] * HH + k0 + kk);
            if (seq) {
                v[q].x = fmaxf(v[q].x, 0.f); v[q].y = fmaxf(v[q].y, 0.f);
                v[q].z = fmaxf(v[q].z, 0.f); v[q].w = fmaxf(v[q].w, 0.f);
            }
        }
    };
    auto storeW = [&](const float4 v[4]) {
#pragma unroll
        for (int q = 0; q < 4; q++) {
            int f = tid + 128 * q;
            int r = f >> 2, kk = (f & 3) * 4;
            As[kk][r] = v[q].x; As[kk+1][r] = v[q].y; As[kk+2][r] = v[q].z; As[kk+3][r] = v[q].w;
        }
    };
    auto storeE = [&](const float4 v[2]) {
#pragma unroll
        for (int q = 0; q < 2; q++) {
            int f = tid + 128 * q;
            int r = f >> 2, kk = (f & 3) * 4;
            Bs[kk][r] = v[q].x; Bs[kk+1][r] = v[q].y; Bs[kk+2][r] = v[q].z; Bs[kk+3][r] = v[q].w;
        }
    };

    unsigned long long acc[4][8];
#pragma unroll
    for (int p = 0; p < 4; p++)
#pragma unroll
        for (int c = 0; c < 8; c++) acc[p][c] = 0ull;

    loadW(vw, 0); loadE(ve, 0);
    storeW(vw);   storeE(ve);
    __syncthreads();

    for (int t = 0; t < HH / 16; t++) {
        float4 nw[4], ne[2];
        if (t < HH / 16 - 1) { loadW(nw, (t + 1) * 16); loadE(ne, (t + 1) * 16); }
#pragma unroll 4
        for (int k = 0; k < 16; k++) {
            ulonglong2 a0 = *(const ulonglong2*)&As[k][ug * 8];
            ulonglong2 a1 = *(const ulonglong2*)&As[k][ug * 8 + 4];
            float4 e0 = *(const float4*)&Bs[k][bg * 8];
            float4 e1 = *(const float4*)&Bs[k][bg * 8 + 4];
            unsigned long long ap[4] = {a0.x, a0.y, a1.x, a1.y};
            unsigned long long bp[8] = {pack2(e0.x), pack2(e0.y), pack2(e0.z), pack2(e0.w),
                                        pack2(e1.x), pack2(e1.y), pack2(e1.z), pack2(e1.w)};
#pragma unroll
            for (int p = 0; p < 4; p++)
#pragma unroll
                for (int c = 0; c < 8; c++) ffma2(acc[p][c], ap[p], bp[c]);
        }
        __syncthreads();
        if (t < HH / 16 - 1) { storeW(nw); storeE(ne); }
        __syncthreads();
    }

    // epilogue: giT[(by*G3 + unit)*64 + batch] (+ per-unit bias)
#pragma unroll
    for (int p = 0; p < 4; p++) {
        const int u0 = n0 + ug * 8 + 2 * p;
        float bia0 = b_ih[u0], bia1 = b_ih[u0 + 1];
        float2 v[8];
#pragma unroll
        for (int c = 0; c < 8; c++) v[c] = unpk2(acc[p][c]);
        float* d0 = g_giT + ((size_t)by * G3 + u0) * BB + bg * 8;
        float* d1 = d0 + BB;
        *(float4*)(d0)     = make_float4(v[0].x + bia0, v[1].x + bia0, v[2].x + bia0, v[3].x + bia0);
        *(float4*)(d0 + 4) = make_float4(v[4].x + bia0, v[5].x + bia0, v[6].x + bia0, v[7].x + bia0);
        *(float4*)(d1)     = make_float4(v[0].y + bia1, v[1].y + bia1, v[2].y + bia1, v[3].y + bia1);
        *(float4*)(d1 + 4) = make_float4(v[4].y + bia1, v[5].y + bia1, v[6].y + bia1, v[7].y + bia1);
    }
}

// ---------------------------------------------------------------------------
// Two-level grid barrier: 16 leaf counters (8 blocks each) -> master -> gen.
__device__ __forceinline__ void gsync(unsigned target)
{
    __syncthreads();
    if (threadIdx.x == 0) {
        unsigned old;
        asm volatile("atom.acq_rel.gpu.global.add.u32 %0, [%1], %2;"
                     : "=r"(old) : "l"(g_leaf + (blockIdx.x & 15u)), "r"(1u) : "memory");
        if ((old & 7u) == 7u) {
            unsigned o2;
            asm volatile("atom.acq_rel.gpu.global.add.u32 %0, [%1], %2;"
                         : "=r"(o2) : "l"(&g_master), "r"(1u) : "memory");
            if ((o2 & 15u) == 15u)
                asm volatile("st.release.gpu.global.u32 [%0], %1;"
                             :: "l"(&g_gen), "r"(target) : "memory");
        }
        unsigned g;
        do {
            asm volatile("ld.acquire.gpu.global.u32 %0, [%1];"
                         : "=r"(g) : "l"(&g_gen) : "memory");
        } while ((int)(g - target) < 0);
    }
    __syncthreads();
}

// ---------------------------------------------------------------------------
// Persistent recurrence, 128 blocks x 256 threads, ONE barrier per step.
// Block owns 6 hidden units -> 18 gh cols. 16 half-warp k-slices (48 k each);
// half-lane: rg = hl&7 (rows rg*8..+7, 4 f32x2 pairs), cg2 = hl>>3 (cols cg2*9..+8).
// Per-SM-per-k: FFMA2 144 cyc >= LDS 136 cyc -> FMA-bound at peak.
// Half-warp partials merged via shfl_xor(16); red = 8 x [64][18] in buf1.
__global__ void __launch_bounds__(RTPB, 1) k_rec(const float* __restrict__ w_hh,
                                                 const float* __restrict__ b_hh)
{
    extern __shared__ __align__(16) float sm[];
    float* ws  = sm;                       // [768][24] padded
    float* hs  = sm + HH * RCP;            // 2 x [256][64]
    float* red = hs + CHK * BB;            // alias buf1: 8 x [64][18] = 36.9KB
    float* ghs = hs + 2 * CHK * BB;        // [64][18]

    const int tid  = threadIdx.x;
    const int u0   = blockIdx.x * UPB;
    const int w    = tid >> 5;             // warp 0..7
    const int lane = tid & 31;
    const int ks   = tid >> 4;             // half-warp k-slice 0..15
    const int hl   = tid & 15;
    const int rg   = hl & 7;               // rows rg*8..+7
    const int cg2  = hl >> 3;              // col group 0..1 -> cols cg2*9..+8

    // preload w slice: ws[k*24 + g2*12 + c] = w_hh[(gate*768 + u0+unit)][k], col=g2*9+c
    for (int idx = tid; idx < HH * RCP; idx += RTPB) {
        int k = idx / RCP, cc = idx - k * RCP;
        int g2 = cc / 12, c = cc - g2 * 12;
        float v = 0.f;
        if (c < 9) {
            int col = g2 * 9 + c;
            int gate = col / UPB, unit = col - gate * UPB;
            v = w_hh[(size_t)(gate * HH + u0 + unit) * HH + k];
        }
        ws[idx] = v;
    }
    // gate biases: t = tid + q*256 -> b = t&63, iu = t>>6 (<6)
    float bh_r[2], bh_z[2], bh_n[2];
#pragma unroll
    for (int q = 0; q < 2; q++) {
        int t = tid + q * RTPB;
        if (t < BB * UPB) {
            int iu = t >> 6;
            bh_r[q] = b_hh[u0 + iu];
            bh_z[q] = b_hh[HH + u0 + iu];
            bh_n[q] = b_hh[2 * HH + u0 + iu];
        }
    }
    __syncthreads();

    const unsigned hsb = (unsigned)__cvta_generic_to_shared(hs);
    auto stage = [&](int ch) {
        const float4* src = (const float4*)(g_hT + (size_t)ch * CHK * BB) + tid;
        unsigned dst = hsb + (unsigned)((ch & 1) * (CHK * BB * 4)) + tid * 16;
#pragma unroll
        for (int j = 0; j < (CHK * BB / 4) / RTPB; j++)   // 16
            cpa16(dst + j * RTPB * 16, src + j * RTPB);
        cpa_commit();
    };

    const unsigned base = *(volatile unsigned*)&g_gen;    // replay-safe offset
    unsigned ngen = 0;

    for (int l = 0; l < NSTEP; l++) {
        stage(0);
        stage(1);

        // prefetch gate operands (batch-contiguous)
        float pre_r[2], pre_z[2], pre_n[2], pre_h[2];
#pragma unroll
        for (int q = 0; q < 2; q++) {
            int t = tid + q * RTPB;
            if (t < BB * UPB) {
                int b = t & 63, iu = t >> 6;
                const float* gp = g_giT + ((size_t)l * G3 + u0 + iu) * BB + b;
                pre_r[q] = __ldcg(gp);
                pre_z[q] = __ldcg(gp + (size_t)HH * BB);
                pre_n[q] = __ldcg(gp + (size_t)2 * HH * BB);
                pre_h[q] = __ldcg(&g_hT[(u0 + iu) * BB + b]);
            }
        }

        unsigned long long acc[4][9];
#pragma unroll
        for (int p = 0; p < 4; p++)
#pragma unroll
            for (int c = 0; c < 9; c++) acc[p][c] = 0ull;

        for (int ch = 0; ch < HH / CHK; ch++) {
            if (ch < HH / CHK - 1) cpa_wait1(); else cpa_wait0();
            __syncthreads();
            const float* hb = hs + (ch & 1) * (CHK * BB);
            const int kb = ks * (CHK / KSL);             // 16 k per slice per chunk
#pragma unroll 4
            for (int kk = 0; kk < CHK / KSL; kk++) {
                const int kl = kb + kk;
                const int kg = ch * CHK + kl;
                ulonglong2 a0 = *(const ulonglong2*)&hb[kl * BB + rg * 8];
                ulonglong2 a1 = *(const ulonglong2*)&hb[kl * BB + rg * 8 + 4];
                const float* wp = &ws[kg * RCP + cg2 * 12];
                float4 w0 = *(const float4*)(wp);
                float4 w1 = *(const float4*)(wp + 4);
                float  w8 = wp[8];
                unsigned long long ap[4] = {a0.x, a0.y, a1.x, a1.y};
                unsigned long long bp[9] = {pack2(w0.x), pack2(w0.y), pack2(w0.z), pack2(w0.w),
                                            pack2(w1.x), pack2(w1.y), pack2(w1.z), pack2(w1.w),
                                            pack2(w8)};
#pragma unroll
                for (int p = 0; p < 4; p++)
#pragma unroll
                    for (int c = 0; c < 9; c++) ffma2(acc[p][c], ap[p], bp[c]);
            }
            __syncthreads();                 // buffer (ch&1) free
            if (ch == 0) stage(2);           // chunk2 -> buf0
        }

        // ---- half-warp merge (shfl_xor 16) + write 8 warp partials to red ----
#pragma unroll
        for (int p = 0; p < 4; p++) {
            const int r0 = rg * 8 + 2 * p;
#pragma unroll
            for (int c = 0; c < 9; c++) {
                float2 v = unpk2(acc[p][c]);
                v.x += __shfl_xor_sync(0xffffffffu, v.x, 16);
                v.y += __shfl_xor_sync(0xffffffffu, v.y, 16);
                if (lane < 16) {
                    red[w * (BB * RC) + r0 * RC + cg2 * 9 + c]       = v.x;
                    red[w * (BB * RC) + (r0 + 1) * RC + cg2 * 9 + c] = v.y;
                }
            }
        }
        __syncthreads();
#pragma unroll
        for (int j = 0; j < 5; j++) {                    // 1152 outputs / 256 thr
            const int o = tid + j * RTPB;
            if (o < BB * RC) {
                float s = red[o];
#pragma unroll
                for (int ww = 1; ww < 8; ww++) s += red[ww * (BB * RC) + o];
                ghs[o] = s;
            }
        }
        __syncthreads();

        // ---- gates (block-local, coalesced h stores) ----
#pragma unroll
        for (int q = 0; q < 2; q++) {
            const int t = tid + q * RTPB;
            if (t < BB * UPB) {
                const int b = t & 63, iu = t >> 6;
                float ghr = ghs[b * RC + iu];
                float ghz = ghs[b * RC + UPB + iu];
                float ghn = ghs[b * RC + 2 * UPB + iu];
                float r = sigmoidf_(pre_r[q] + ghr + bh_r[q]);
                float z = sigmoidf_(pre_z[q] + ghz + bh_z[q]);
                float n = tanhf(pre_n[q] + r * (ghn + bh_n[q]));
                float h = (1.f - z) * n + z * pre_h[q];
                if (l < LL) h = fmaxf(h, 0.f);     // final step NOT relu'd
                __stcg(&g_hT[(u0 + iu) * BB + b], h);
                if (l == LL) g_hbm[(size_t)b * HH + u0 + iu] = h;
            }
        }

        ++ngen;
        gsync(base + ngen);   // ONE barrier per step
    }
}

// ---------------------------------------------------------------------------
// Scorer: warp-per-neuron, weights in registers; device globals referenced
// directly in device code (host may not pass __device__ symbols).
__global__ void __launch_bounds__(256) k_mlp0(const float* __restrict__ w,
                                              const float* __restrict__ bias)
{
    const int warp = threadIdx.x >> 5;
    const int lane = threadIdx.x & 31;
    const int n = blockIdx.x * 8 + warp;

    float4 wr[6];
    const float* wrow = w + (size_t)n * HH + lane * 24;
#pragma unroll
    for (int i = 0; i < 6; i++) wr[i] = *(const float4*)(wrow + i * 4);
    const float bn = bias[n];

    for (int b = 0; b < BB; b++) {
        const float* xr = g_hbm + (size_t)b * HH + lane * 24;
        float s = 0.f;
#pragma unroll
        for (int i = 0; i < 6; i++) {
            float4 xv = *(const float4*)(xr + i * 4);
            s += xv.x * wr[i].x + xv.y * wr[i].y + xv.z * wr[i].z + xv.w * wr[i].w;
        }
#pragma unroll
        for (int off = 16; off; off >>= 1) s += __shfl_xor_sync(0xffffffffu, s, off);
        if (lane == 0) g_s1[(size_t)b * HH + n] = fmaxf(s + bn, 0.f);
    }
}

__global__ void __launch_bounds__(256) k_mlp1(const float* __restrict__ w,
                                              const float* __restrict__ bias)
{
    const int warp = threadIdx.x >> 5;
    const int lane = threadIdx.x & 31;
    const int n = blockIdx.x * 8 + warp;

    float4 wr[6];
    const float* wrow = w + (size_t)n * HH + lane * 24;
#pragma unroll
    for (int i = 0; i < 6; i++) wr[i] = *(const float4*)(wrow + i * 4);
    const float bn = bias[n];

    for (int b = 0; b < BB; b++) {
        const float* xr = g_s1 + (size_t)b * HH + lane * 24;
        float s = 0.f;
#pragma unroll
        for (int i = 0; i < 6; i++) {
            float4 xv = *(const float4*)(xr + i * 4);
            s += xv.x * wr[i].x + xv.y * wr[i].y + xv.z * wr[i].z + xv.w * wr[i].w;
        }
#pragma unroll
        for (int off = 16; off; off >>= 1) s += __shfl_xor_sync(0xffffffffu, s, off);
        if (lane == 0) g_s2[(size_t)b * HH + n] = fmaxf(s + bn, 0.f);
    }
}

__global__ void __launch_bounds__(256) k_final(const float* __restrict__ swo,
                                               const float* __restrict__ sbo,
                                               float* __restrict__ out)
{
    const int warp = threadIdx.x >> 5;
    const int lane = threadIdx.x & 31;
    const int b = blockIdx.x * 8 + warp;
    const float* xr = g_s2 + (size_t)b * HH + lane * 24;
    const float* wr = swo + lane * 24;
    float s = 0.f;
#pragma unroll
    for (int i = 0; i < 6; i++) {
        float4 xv = *(const float4*)(xr + i * 4);
        float4 wv = *(const float4*)(wr + i * 4);
        s += xv.x * wv.x + xv.y * wv.y + xv.z * wv.z + xv.w * wv.w;
    }
#pragma unroll
    for (int off = 16; off; off >>= 1) s += __shfl_xor_sync(0xffffffffu, s, off);
    if (lane == 0) out[b] = s + sbo[0];
}

// ---------------------------------------------------------------------------
extern "C" void kernel_launch(void* const* d_in, const int* in_sizes, int n_in,
                              void* d_out, int out_size)
{
    const int*   goal = (const int*)  d_in[0];
    const float* emb  = (const float*)d_in[1];
    const float* w_ih = (const float*)d_in[2];
    const float* w_hh = (const float*)d_in[3];
    const float* b_ih = (const float*)d_in[4];
    const float* b_hh = (const float*)d_in[5];
    const float* sw0  = (const float*)d_in[6];
    const float* sb0  = (const float*)d_in[7];
    const float* sw1  = (const float*)d_in[8];
    const float* sb1  = (const float*)d_in[9];
    const float* swo  = (const float*)d_in[10];
    const float* sbo  = (const float*)d_in[11];
    float* out = (float*)d_out;

    const int smem_rec = (HH * RCP + 2 * CHK * BB + BB * RC) * (int)sizeof(float); // 204.5KB
    cudaFuncSetAttribute(k_rec, cudaFuncAttributeMaxDynamicSharedMemorySize, smem_rec);

    k_init<<<(BB * HH + 255) / 256, 256>>>();
    k_gi<<<dim3(G3 / 128, NSTEP), 128>>>(goal, emb, w_ih, b_ih);
    k_rec<<<RBLK, RTPB, smem_rec>>>(w_hh, b_hh);
    k_mlp0<<<HH / 8, 256>>>(sw0, sb0);
    k_mlp1<<<HH / 8, 256>>>(sw1, sb1);
    k_final<<<BB / 8, 256>>>(swo, sbo, out);
}